// round 17
// baseline (speedup 1.0000x reference)
#include <cuda_runtime.h>

#define TT 65536
#define HH 50
#define RR 200      // 4*H gate rows
#define PC 208      // padded row stride of precompute buffer (floats)
#define PNT 224     // precompute threads
#define LT 224      // lstm threads: 50 elements x 4 gates (+ 24 idle lanes)
#define HP 56       // padded h vector length (56 floats = 14 x 16B)

// Precomputed: P[t][0..199] = W_ih1[:, :7] @ x_t[:7] + b_ih1 + b_hh1 ; P[t][200] = x_t[7]
__device__ float g_P[(size_t)TT * PC];

static __device__ __forceinline__ unsigned long long pk2(float a, float b){
    unsigned long long r; asm("mov.b64 %0, {%1, %2};" : "=l"(r) : "f"(a), "f"(b)); return r;
}
static __device__ __forceinline__ void fma2(unsigned long long& acc, unsigned long long a, unsigned long long b){
    asm("fma.rn.f32x2 %0, %1, %2, %0;" : "+l"(acc) : "l"(a), "l"(b));
}
static __device__ __forceinline__ void add2(unsigned long long& acc, unsigned long long a){
    asm("add.rn.f32x2 %0, %0, %1;" : "+l"(acc) : "l"(a));
}
static __device__ __forceinline__ float upksum(unsigned long long v){
    float x, y; asm("mov.b64 {%0, %1}, %2;" : "=f"(x), "=f"(y) : "l"(v)); return x + y;
}
static __device__ __forceinline__ float tanhap(float x){
    float r; asm("tanh.approx.f32 %0, %1;" : "=f"(r) : "f"(x)); return r;
}

// ---------------------------------------------------------------------------
// Kernel 1: parallel precompute of the err-independent part of layer-1 gates.
// ---------------------------------------------------------------------------
__global__ void precompute_kernel(const float* __restrict__ x,
                                  const float* __restrict__ Wih1,
                                  const float* __restrict__ bih1,
                                  const float* __restrict__ bhh1)
{
    int t = blockIdx.x;
    int j = threadIdx.x;
    const float* xr = x + t * 8;
    if (j < RR){
        float acc = bih1[j] + bhh1[j];
        const float* w = Wih1 + j * 8;
        #pragma unroll
        for (int k = 0; k < 7; k++) acc = fmaf(w[k], xr[k], acc);
        g_P[(size_t)t * PC + j] = acc;
    } else if (j == RR){
        g_P[(size_t)t * PC + RR] = xr[7];   // act_dist
    }
}

// ---------------------------------------------------------------------------
// Kernel 2: persistent single-block sequential LSTM scan, 7 warps.
// Thread tid = e*4 + q (e=element, q=gate i/f/g/o); tids 200..223 idle-ish
// (zero weights, never store). Each thread computes FULL 50-wide dots
// (14 LDS.128 per h vector, broadcast). 2 __syncthreads per step.
//   A: v1 = s1pre + werr*err; act; 3-shfl fixed butterfly; cell1 -> sh1[e]
//   B: dots wi2@h1, wh2@h2, pre-dot wh1@h1 (h1 loads shared); act; full
//      butterfly (all lanes valid); cell2 -> sh2; y via xor4/8/16 shfls
//      (py identical within each 4-lane group, so the bits-2..4 butterfly
//       counts every element exactly ONCE -> no scale factor)
//   C: y from 7 warp partials (2 LDS.128), err update, redundant all-thread
// ---------------------------------------------------------------------------
__global__ void __launch_bounds__(LT, 1) lstm_kernel(
    const float* __restrict__ Wih1, const float* __restrict__ Whh1,
    const float* __restrict__ Wih2, const float* __restrict__ Whh2,
    const float* __restrict__ bih2, const float* __restrict__ bhh2,
    const float* __restrict__ Wout, const float* __restrict__ bout,
    float* __restrict__ out)
{
    const int tid  = threadIdx.x;
    const int e    = tid >> 2;
    const int q    = tid & 3;
    const int wid  = tid >> 5;
    const int lane = tid & 31;
    const bool isrow = (tid < RR);
    const int row  = isrow ? (q * HH + e) : 0;
    const unsigned gmask = 0xFu << (lane & 28);       // 4-lane group mask

    // activation: act = ka * tanh(ka*v) + kc  (tanh for g; sigmoid otherwise)
    const float ka = (q == 2) ? 1.f : 0.5f;
    const float kc = (q == 2) ? 0.f : 0.5f;

    // ---- register-resident weights: full rows, f32x2 packed, zero-padded ----
    unsigned long long wh1[28], wi2[28], wh2[28];
    {
        const float* a = Whh1 + row * HH;
        const float* b = Wih2 + row * HH;
        const float* c = Whh2 + row * HH;
        #pragma unroll
        for (int k = 0; k < 28; k++){
            int i0 = 2 * k, i1 = i0 + 1;
            bool v0 = isrow && (i0 < HH), v1 = isrow && (i1 < HH);
            wh1[k] = pk2(v0 ? a[i0] : 0.f, v1 ? a[i1] : 0.f);
            wi2[k] = pk2(v0 ? b[i0] : 0.f, v1 ? b[i1] : 0.f);
            wh2[k] = pk2(v0 ? c[i0] : 0.f, v1 ? c[i1] : 0.f);
        }
    }
    const float werr   = isrow ? Wih1[row * 8 + 7] : 0.f;
    const float b2     = isrow ? (bih2[row] + bhh2[row]) : 0.f;
    const float bo     = bout[0];
    const float wout_e = (e < HH) ? Wout[e] : 0.f;

    __shared__ __align__(16) float sh1[HP];           // single-buffered
    __shared__ __align__(16) float sh2[2][HP];        // ping-pong
    __shared__ __align__(16) float sh_part[8];        // 7 warp partials + pad
    if (tid < HP){ sh1[tid] = 0.f; sh2[0][tid] = 0.f; sh2[1][tid] = 0.f; }
    if (tid < 8) sh_part[tid] = 0.f;                  // index 7 stays zero

    float c1 = 0.f, c2 = 0.f, err = 0.f;
    float s1pre  = g_P[row];                          // P(0) + Whh1@h1(-1)=0
    float ad_cur = g_P[RR];
    __syncthreads();

    int cb = 0;
    for (int t = 0; t < TT; t++){
        const int pb = cb ^ 1;

        // prefetch next step's P row + act_dist (consumed in B / next C)
        const int tn = (t + 1 < TT) ? (t + 1) : t;
        const float p_next  = g_P[(size_t)tn * PC + row];
        const float ad_next = g_P[(size_t)tn * PC + RR];

        // ============ phase A: layer-1 activation + cell (no LDS) ============
        {
            float v = fmaf(werr, err, s1pre);
            float act = fmaf(ka, tanhap(ka * v), kc);

            // fixed assignment: valid in q==0 lanes (the writers)
            float s1 = __shfl_xor_sync(gmask, act, 1);   // q^1
            float s2 = __shfl_xor_sync(gmask, act, 2);   // q^2
            float s3 = __shfl_xor_sync(gmask, s1, 2);    // q^3
            c1 = fmaf(s1, c1, act * s2);                 // f*c + i*g (q==0 view)
            float h1v = s3 * tanhap(c1);                 // o * tanh(c)
            if (q == 0 && isrow) sh1[e] = h1v;
        }
        __syncthreads();

        // ====== phase B: layer-2 gates+cell AND pre-dot for next layer-1 ======
        float s1pre_next;
        {
            unsigned long long a0 = 0ull, a1 = 0ull, d0 = 0ull, d1 = 0ull;
            unsigned long long p0 = 0ull, p1 = 0ull;
            const ulonglong2* hb1 = (const ulonglong2*)sh1;
            const ulonglong2* hb2 = (const ulonglong2*)sh2[pb];
            #pragma unroll
            for (int k = 0; k < 14; k++){
                ulonglong2 u = hb1[k];                   // h1 (broadcast)
                ulonglong2 w = hb2[k];                   // h2 (broadcast)
                fma2(a0, wi2[2*k],   u.x);  fma2(a1, wi2[2*k+1], u.y);
                fma2(d0, wh2[2*k],   w.x);  fma2(d1, wh2[2*k+1], w.y);
                fma2(p0, wh1[2*k],   u.x);  fma2(p1, wh1[2*k+1], u.y);
            }
            float s  = (upksum(a0) + upksum(a1)) + (upksum(d0) + upksum(d1));
            s1pre_next = (upksum(p0) + upksum(p1)) + p_next;  // Whh1@h1(t)+P(t+1)

            float v = s + b2;
            float act = fmaf(ka, tanhap(ka * v), kc);

            // full butterfly: all lanes get valid (i,f,g,o)
            float s1 = __shfl_xor_sync(gmask, act, 1);
            float s2 = __shfl_xor_sync(gmask, act, 2);
            float s3 = __shfl_xor_sync(gmask, s1, 2);
            float gi, gf, gg, go;
            if      (q == 0){ gi = act; gf = s1;  gg = s2;  go = s3;  }
            else if (q == 1){ gi = s1;  gf = act; gg = s3;  go = s2;  }
            else if (q == 2){ gi = s2;  gf = s3;  gg = act; go = s1;  }
            else            { gi = s3;  gf = s2;  gg = s1;  go = act; }
            c2 = fmaf(gf, c2, gi * gg);
            float h2v = go * tanhap(c2);
            if (q == 0 && isrow) sh2[cb][e] = h2v;

            // y partial: py identical across each 4-lane group; xor over bits
            // 2..4 sums ONE lane per group -> each element counted exactly once
            float py = wout_e * h2v;                     // 0 in idle lanes
            py += __shfl_xor_sync(0xFFFFFFFFu, py, 4);
            py += __shfl_xor_sync(0xFFFFFFFFu, py, 8);
            py += __shfl_xor_sync(0xFFFFFFFFu, py, 16);
            if (lane == 0) sh_part[wid] = py;
        }
        __syncthreads();

        // ====== phase C: y + err from 7 partials (redundant, no barrier) ======
        {
            unsigned long long s0 = 0ull, s1 = 0ull;
            const ulonglong2* pp = (const ulonglong2*)sh_part;
            ulonglong2 v0 = pp[0], v1 = pp[1];
            add2(s0, v0.x); add2(s1, v0.y);
            add2(s0, v1.x); add2(s1, v1.y);
            float y = (upksum(s0) + upksum(s1)) + bo;
            if (tid == 0) out[t] = y;
            err = fmaf(0.9f, err, 0.1f * (ad_cur - y));
        }

        s1pre = s1pre_next; ad_cur = ad_next; cb ^= 1;
    }
}

extern "C" void kernel_launch(void* const* d_in, const int* in_sizes, int n_in,
                              void* d_out, int out_size)
{
    const float* x    = (const float*)d_in[0];
    const float* Wih1 = (const float*)d_in[1];
    const float* Whh1 = (const float*)d_in[2];
    const float* bih1 = (const float*)d_in[3];
    const float* bhh1 = (const float*)d_in[4];
    const float* Wih2 = (const float*)d_in[5];
    const float* Whh2 = (const float*)d_in[6];
    const float* bih2 = (const float*)d_in[7];
    const float* bhh2 = (const float*)d_in[8];
    const float* Wout = (const float*)d_in[9];
    const float* bout = (const float*)d_in[10];
    float* out = (float*)d_out;

    precompute_kernel<<<TT, PNT>>>(x, Wih1, bih1, bhh1);
    lstm_kernel<<<1, LT>>>(Wih1, Whh1, Wih2, Whh2, bih2, bhh2, Wout, bout, out);
}